// round 5
// baseline (speedup 1.0000x reference)
#include <cuda_runtime.h>

// CCSDS-123 lossless predictor: vectorized causal stencil over [Z=224, Y=512, X=512].
// Outputs 6 planes concatenated: predictions, residuals, quantized_residuals,
// mapped_indices (as float), sample_representatives, reconstructed.

#define ZB 224
#define YB 512
#define XB 512

static constexpr size_t PLANE = (size_t)ZB * YB * XB;   // 58,720,256

__global__ __launch_bounds__(128) void ccsds123_kernel(
    const float* __restrict__ img, float* __restrict__ out)
{
    const int zy  = blockIdx.x;        // z*512 + y
    const int z   = zy >> 9;
    const int y   = zy & 511;
    const int tid = threadIdx.x;

    __shared__ float sc[XB];   // center row s(z, y, :)
    __shared__ float sn[XB];   // north row  s(z, y-1, :)
    __shared__ float sp[XB];   // prev band  s(z-1, y, :)

    const float* crow = img + (size_t)zy * XB;

    // Stage rows into shared memory (float4 vectorized; zeros for missing rows)
    ((float4*)sc)[tid] = ((const float4*)crow)[tid];
    ((float4*)sn)[tid] = (y > 0) ? ((const float4*)(crow - XB))[tid]
                                 : make_float4(0.f, 0.f, 0.f, 0.f);
    ((float4*)sp)[tid] = (z > 0) ? ((const float4*)(crow - (size_t)YB * XB))[tid]
                                 : make_float4(0.f, 0.f, 0.f, 0.f);
    __syncthreads();

    const int x0 = tid * 4;
    float pr[4], rs[4], mp[4], rc[4];

#pragma unroll
    for (int j = 0; j < 4; j++) {
        const int x = x0 + j;
        const float C   = sc[x];
        const float Wv  = (x > 0)      ? sc[x - 1] : 0.f;
        const float Nv  = sn[x];
        const float NWv = (x > 0)      ? sn[x - 1] : 0.f;
        const float NEv = (x < XB - 1) ? sn[x + 1] : 0.f;

        // neighbor-oriented local sum with edge cases
        float sigma;
        if (y == 0)           sigma = (x == 0) ? 0.f : 4.f * Wv;   // top row
        else if (x == 0)      sigma = 2.f * (Nv + NEv);            // left col
        else if (x == XB - 1) sigma = Wv + NWv + 2.f * Nv;         // right col
        else                  sigma = Wv + NWv + Nv + NEv;         // interior

        const float spred = sigma * 0.25f;
        const float pb    = sp[x];

        float p = (z == 0) ? spred : 0.5f * (spred + pb);
        if (y == 0 && x == 0) p = (z == 0) ? 0.f : pb;             // origin sample

        const float r = C - p;                     // residual (== quantized residual)
        const float q = rintf(r);                  // half-to-even, matches jnp.round
        const float m = (q >= 0.f) ? (2.f * q) : (-2.f * q - 1.f); // zigzag map
        const float rec = fminf(fmaxf(p + r, -32768.f), 32767.f);  // clip

        pr[j] = p; rs[j] = r; mp[j] = m; rc[j] = rec;
    }

    const size_t off = (size_t)zy * XB + (size_t)x0;
    *(float4*)(out + off)             = *(const float4*)pr;  // predictions
    *(float4*)(out + off + PLANE)     = *(const float4*)rs;  // residuals
    *(float4*)(out + off + 2 * PLANE) = *(const float4*)rs;  // quantized residuals
    *(float4*)(out + off + 3 * PLANE) = *(const float4*)mp;  // mapped indices
    *(float4*)(out + off + 4 * PLANE) = *(const float4*)rc;  // sample representatives
    *(float4*)(out + off + 5 * PLANE) = *(const float4*)rc;  // reconstructed
}

extern "C" void kernel_launch(void* const* d_in, const int* in_sizes, int n_in,
                              void* d_out, int out_size)
{
    const float* img = (const float*)d_in[0];
    float* out = (float*)d_out;
    // one block per (z, y) row; 128 threads x float4 over x
    ccsds123_kernel<<<ZB * YB, 128>>>(img, out);
}